// round 1
// baseline (speedup 1.0000x reference)
#include <cuda_runtime.h>

#define N_    2
#define CIN   32
#define T_    8
#define H_    56
#define W_    56
#define COUT  64
#define KVOL  27
#define SP    25088   // T*H*W = To*Ho*Wo
#define HW    3136    // H*W

// Scratch (no allocations allowed in kernel_launch)
__device__ float g_xt[(size_t)N_ * SP * CIN];     // x transposed to [N, T*H*W, C]
__device__ float g_wt[KVOL * CIN * COUT];         // weight transposed to [k][c][co]

// ---------------------------------------------------------------------------
// x: [N, C, T*H*W]  ->  g_xt: [N, T*H*W, C]   (C=32 innermost for coalesced gathers)
// ---------------------------------------------------------------------------
__global__ __launch_bounds__(256) void transpose_x(const float* __restrict__ x) {
    __shared__ float sm[32][33];
    int n  = blockIdx.y;
    int s0 = blockIdx.x * 32;
    int tx = threadIdx.x & 31;
    int ty = threadIdx.x >> 5;        // 0..7
#pragma unroll
    for (int r = 0; r < 4; ++r) {
        int c = ty + r * 8;
        sm[c][tx] = x[((size_t)n * CIN + c) * SP + s0 + tx];   // coalesced read
    }
    __syncthreads();
#pragma unroll
    for (int r = 0; r < 4; ++r) {
        int j = ty + r * 8;
        g_xt[((size_t)n * SP + s0 + j) * CIN + tx] = sm[tx][j]; // coalesced write
    }
}

// ---------------------------------------------------------------------------
// weight: [co, c, k]  ->  g_wt: [k, c, co]
// ---------------------------------------------------------------------------
__global__ void transpose_w(const float* __restrict__ w) {
    int i = blockIdx.x * blockDim.x + threadIdx.x;
    if (i >= KVOL * CIN * COUT) return;
    int k  = i / (CIN * COUT);
    int r  = i - k * (CIN * COUT);
    int c  = r >> 6;
    int co = r & 63;
    g_wt[i] = w[((size_t)co * CIN + c) * KVOL + k];
}

// ---------------------------------------------------------------------------
// Main fused kernel: per block = 32 output positions (one n).
// For each of the 27 taps:
//   phase 1: 8 warps (4 positions each, lane = channel) build col[pos][c] via
//            trilinear gather from g_xt (each corner = one 128B vector load)
//   phase 2: 256 threads, each owns a 2(cout) x 4(pos) register tile;
//            rank-32 update from col + staged weight slice.
// ---------------------------------------------------------------------------
__global__ __launch_bounds__(256) void deform_conv3d_main(
    const float* __restrict__ offset,
    const float* __restrict__ bias,
    float* __restrict__ out)
{
    __shared__ float col[32 * 32];   // [pos][c]
    __shared__ float wsm[2048];      // [c][co] slice for current k; reused as [co][pos] epilogue

    int n   = blockIdx.y;
    int s0  = blockIdx.x * 32;
    int tid = threadIdx.x;
    int lane   = tid & 31;           // channel in phase 1
    int warpId = tid >> 5;           // 0..7
    int cp = tid & 31;               // cout pair index in phase 2 (co = 2cp, 2cp+1)
    int pq = tid >> 5;               // position quad in phase 2

    float acc[8];
#pragma unroll
    for (int i = 0; i < 8; ++i) acc[i] = 0.f;

    const float* xb = g_xt + (size_t)n * SP * CIN;

    for (int k = 0; k < KVOL; ++k) {
        __syncthreads();   // protect col/wsm of previous iteration

        // stage weight slice [c][co] for this tap (coalesced from g_wt)
#pragma unroll
        for (int i = 0; i < 8; ++i)
            wsm[tid + i * 256] = g_wt[k * 2048 + tid + i * 256];

        int kt = k / 9, kh = (k % 9) / 3, kw = k % 3;

        // ---- phase 1: build column tile ----
#pragma unroll
        for (int pp = 0; pp < 4; ++pp) {
            int q  = warpId * 4 + pp;
            int s  = s0 + q;
            int to = s / HW;
            int rem = s - to * HW;
            int ho = rem / W_;
            int wo = rem - ho * W_;

            const float* offp = offset + ((size_t)n * 81 + k * 3) * SP + s;
            float pt = (float)(to - 1 + kt) + offp[0];          // broadcast loads
            float ph = (float)(ho - 1 + kh) + offp[SP];
            float pw = (float)(wo - 1 + kw) + offp[2 * SP];

            float tf = floorf(pt), hf = floorf(ph), wf = floorf(pw);
            int t0 = (int)tf, h0 = (int)hf, w0 = (int)wf;
            float lt = pt - tf, lh = ph - hf, lw = pw - wf;

            float val = 0.f;
#pragma unroll
            for (int ct = 0; ct < 2; ++ct) {
                int ti = t0 + ct;
                float wt = ct ? lt : 1.f - lt;
                if (ti < 0 || ti >= T_) continue;               // warp-uniform
#pragma unroll
                for (int ch = 0; ch < 2; ++ch) {
                    int hi = h0 + ch;
                    float wh = ch ? lh : 1.f - lh;
                    if (hi < 0 || hi >= H_) continue;
#pragma unroll
                    for (int cw = 0; cw < 2; ++cw) {
                        int wi = w0 + cw;
                        float ww = cw ? lw : 1.f - lw;
                        if (wi < 0 || wi >= W_) continue;
                        val += wt * wh * ww *
                               xb[(size_t)((ti * H_ + hi) * W_ + wi) * CIN + lane];
                    }
                }
            }
            col[q * 32 + lane] = val;
        }
        __syncthreads();

        // ---- phase 2: rank-32 FMA update (2 cout x 4 pos per thread) ----
#pragma unroll
        for (int c = 0; c < 32; ++c) {
            float2 w01 = *(const float2*)&wsm[c * 64 + 2 * cp];  // conflict-free
#pragma unroll
            for (int j = 0; j < 4; ++j) {
                float v = col[(pq * 4 + j) * 32 + c];            // warp broadcast
                acc[j]     += w01.x * v;
                acc[4 + j] += w01.y * v;
            }
        }
    }

    // ---- epilogue: stage through smem for coalesced global stores ----
    __syncthreads();
#pragma unroll
    for (int j = 0; j < 4; ++j) {
        wsm[(2 * cp)     * 32 + pq * 4 + j] = acc[j];
        wsm[(2 * cp + 1) * 32 + pq * 4 + j] = acc[4 + j];
    }
    __syncthreads();
#pragma unroll
    for (int i = 0; i < 8; ++i) {
        int idx = tid + i * 256;
        int co = idx >> 5, p = idx & 31;
        out[((size_t)n * COUT + co) * SP + s0 + p] = wsm[idx] + bias[co];
    }
}

// ---------------------------------------------------------------------------
extern "C" void kernel_launch(void* const* d_in, const int* in_sizes, int n_in,
                              void* d_out, int out_size) {
    const float* x      = (const float*)d_in[0];
    const float* offset = (const float*)d_in[1];
    const float* weight = (const float*)d_in[2];
    const float* bias   = (const float*)d_in[3];
    float* out = (float*)d_out;

    dim3 gT(SP / 32, N_);
    transpose_x<<<gT, 256>>>(x);
    transpose_w<<<(KVOL * CIN * COUT + 255) / 256, 256>>>(weight);

    dim3 gM(SP / 32, N_);
    deform_conv3d_main<<<gM, 256>>>(offset, bias, out);
}

// round 2
// speedup vs baseline: 1.3113x; 1.3113x over previous
#include <cuda_runtime.h>

#define N_    2
#define CIN   32
#define T_    8
#define H_    56
#define W_    56
#define COUT  64
#define KVOL  27
#define SP    25088   // T*H*W
#define HW    3136    // H*W

// Scratch (no allocations allowed in kernel_launch)
__device__ float g_xt[(size_t)N_ * SP * CIN];     // x transposed to [N, T*H*W, C]
__device__ float g_wt[KVOL * CIN * COUT];         // weight transposed to [k][c][co]

// ---- packed f32x2 helpers (Blackwell) -------------------------------------
__device__ __forceinline__ unsigned long long ffma2(unsigned long long a,
                                                    unsigned long long b,
                                                    unsigned long long c) {
    unsigned long long d;
    asm("fma.rn.f32x2 %0, %1, %2, %3;" : "=l"(d) : "l"(a), "l"(b), "l"(c));
    return d;
}
__device__ __forceinline__ unsigned long long pack2(float x) {
    unsigned long long d;
    asm("mov.b64 %0, {%1, %2};" : "=l"(d) : "f"(x), "f"(x));
    return d;
}
__device__ __forceinline__ void unpack2(unsigned long long v, float& lo, float& hi) {
    asm("mov.b64 {%0, %1}, %2;" : "=f"(lo), "=f"(hi) : "l"(v));
}

// ---------------------------------------------------------------------------
// x: [N, C, T*H*W]  ->  g_xt: [N, T*H*W, C]
// ---------------------------------------------------------------------------
__global__ __launch_bounds__(256) void transpose_x(const float* __restrict__ x) {
    __shared__ float sm[32][33];
    int n  = blockIdx.y;
    int s0 = blockIdx.x * 32;
    int tx = threadIdx.x & 31;
    int ty = threadIdx.x >> 5;
#pragma unroll
    for (int r = 0; r < 4; ++r) {
        int c = ty + r * 8;
        sm[c][tx] = x[((size_t)n * CIN + c) * SP + s0 + tx];
    }
    __syncthreads();
#pragma unroll
    for (int r = 0; r < 4; ++r) {
        int j = ty + r * 8;
        g_xt[((size_t)n * SP + s0 + j) * CIN + tx] = sm[tx][j];
    }
}

// weight: [co, c, k] -> g_wt: [k, c, co]
__global__ void transpose_w(const float* __restrict__ w) {
    int i = blockIdx.x * blockDim.x + threadIdx.x;
    if (i >= KVOL * CIN * COUT) return;
    int k  = i / (CIN * COUT);
    int r  = i - k * (CIN * COUT);
    int c  = r >> 6;
    int co = r & 63;
    g_wt[i] = w[((size_t)co * CIN + c) * KVOL + k];
}

// ---------------------------------------------------------------------------
// Main fused kernel. Block = 64 output positions, all 64 couts, 256 threads.
// col smem layout: [pos_pair (32)][channel (32)][parity (2)]  (8KB)
//   -> phase-2 reads one u64 per (c, pos-pair): natural f32x2, no swizzle.
// ---------------------------------------------------------------------------
__global__ __launch_bounds__(256) void deform_conv3d_main(
    const float* __restrict__ offset,
    const float* __restrict__ bias,
    float* __restrict__ out)
{
    __shared__ float col[32 * 64];   // pair-major: [(q>>1)][c*2 + (q&1)]
    __shared__ float wsm[2048];      // [c][co] slice for current tap
    __shared__ float osm[81 * 64];   // offsets for this block: [ch][q]

    const int n   = blockIdx.y;
    const int s0  = blockIdx.x * 64;
    const int tid = threadIdx.x;
    const int lane   = tid & 31;     // channel in phase 1
    const int warpId = tid >> 5;     // 0..7
    const int cg = tid & 15;         // phase 2: cout group (4 couts)
    const int pg = tid >> 4;         // phase 2: pos group  (4 positions)

    // Stage all offsets for this block's 64 positions (coalesced, once)
    for (int i = tid; i < 81 * 64; i += 256) {
        int ch = i >> 6, j = i & 63;
        osm[i] = offset[((size_t)n * 81 + ch) * SP + s0 + j];
    }

    // Cache base sampling coords for the 8 positions this warp gathers
    float btc[8], bhc[8], bwc[8];
#pragma unroll
    for (int pp = 0; pp < 8; ++pp) {
        int s  = s0 + warpId * 8 + pp;
        int to = s / HW;
        int rem = s - to * HW;
        int ho = rem / W_;
        int wo = rem - ho * W_;
        btc[pp] = (float)(to - 1);
        bhc[pp] = (float)(ho - 1);
        bwc[pp] = (float)(wo - 1);
    }

    unsigned long long acc[4][2];
#pragma unroll
    for (int i = 0; i < 4; ++i) { acc[i][0] = 0ull; acc[i][1] = 0ull; }

    const float* __restrict__ xb = g_xt + (size_t)n * SP * CIN;
    __syncthreads();   // osm ready

    for (int k = 0; k < KVOL; ++k) {
        // stage weight slice [c][co] for this tap (vectorized, coalesced)
        {
            const float4* wg = (const float4*)(g_wt + k * 2048);
            float4* ws = (float4*)wsm;
            ws[tid]       = wg[tid];
            ws[tid + 256] = wg[tid + 256];
        }

        int kt = k / 9;
        int r9 = k - kt * 9;
        int kh = r9 / 3;
        int kw = r9 - kh * 3;
        float ktf = (float)kt, khf = (float)kh, kwf = (float)kw;
        const float* o0 = osm + (k * 3 + 0) * 64;
        const float* o1 = osm + (k * 3 + 1) * 64;
        const float* o2 = osm + (k * 3 + 2) * 64;

        // ---- phase 1: trilinear gather into col ----
#pragma unroll
        for (int pp = 0; pp < 8; ++pp) {
            int q = warpId * 8 + pp;
            float pt = btc[pp] + ktf + o0[q];
            float ph = bhc[pp] + khf + o1[q];
            float pw = bwc[pp] + kwf + o2[q];
            float tf = floorf(pt), hf = floorf(ph), wf = floorf(pw);
            int t0 = (int)tf, h0 = (int)hf, w0 = (int)wf;
            float lt = pt - tf, lh = ph - hf, lw = pw - wf;

            float val;
            if (t0 >= 0 && t0 <= T_ - 2 && h0 >= 0 && h0 <= H_ - 2 &&
                w0 >= 0 && w0 <= W_ - 2) {
                // interior fast path: 8 unguarded vector loads + factored trilerp
                const float* p = xb + ((size_t)((t0 * H_ + h0) * W_ + w0) << 5) + lane;
                float v000 = p[0],        v001 = p[32];
                float v010 = p[W_ * 32],  v011 = p[W_ * 32 + 32];
                const float* p1 = p + HW * 32;
                float v100 = p1[0],       v101 = p1[32];
                float v110 = p1[W_ * 32], v111 = p1[W_ * 32 + 32];
                float c00 = v000 + lw * (v001 - v000);
                float c01 = v010 + lw * (v011 - v010);
                float c10 = v100 + lw * (v101 - v100);
                float c11 = v110 + lw * (v111 - v110);
                float c0 = c00 + lh * (c01 - c00);
                float c1 = c10 + lh * (c11 - c10);
                val = c0 + lt * (c1 - c0);
            } else {
                val = 0.f;
#pragma unroll
                for (int ct = 0; ct < 2; ++ct) {
                    int ti = t0 + ct;
                    float wt = ct ? lt : 1.f - lt;
                    if (ti < 0 || ti >= T_) continue;
#pragma unroll
                    for (int ch = 0; ch < 2; ++ch) {
                        int hi = h0 + ch;
                        float wh = ch ? lh : 1.f - lh;
                        if (hi < 0 || hi >= H_) continue;
#pragma unroll
                        for (int cw = 0; cw < 2; ++cw) {
                            int wi = w0 + cw;
                            float ww = cw ? lw : 1.f - lw;
                            if (wi < 0 || wi >= W_) continue;
                            val += wt * wh * ww *
                                   xb[((size_t)((ti * H_ + hi) * W_ + wi) << 5) + lane];
                        }
                    }
                }
            }
            col[(q >> 1) * 64 + (lane << 1) + (q & 1)] = val;
        }
        __syncthreads();

        // ---- phase 2: rank-32 update, 4 cout x 4 pos, packed f32x2 ----
        {
            const float* crow0 = col + (pg << 7);        // pair 2*pg
            const float* crow1 = crow0 + 64;             // pair 2*pg+1
            const float* wrow  = wsm + (cg << 2);
#pragma unroll
            for (int c = 0; c < 32; ++c) {
                float4 w4 = *(const float4*)(wrow + c * 64);
                unsigned long long v0 = *(const unsigned long long*)(crow0 + (c << 1));
                unsigned long long v1 = *(const unsigned long long*)(crow1 + (c << 1));
                unsigned long long wd;
                wd = pack2(w4.x); acc[0][0] = ffma2(wd, v0, acc[0][0]); acc[0][1] = ffma2(wd, v1, acc[0][1]);
                wd = pack2(w4.y); acc[1][0] = ffma2(wd, v0, acc[1][0]); acc[1][1] = ffma2(wd, v1, acc[1][1]);
                wd = pack2(w4.z); acc[2][0] = ffma2(wd, v0, acc[2][0]); acc[2][1] = ffma2(wd, v1, acc[2][1]);
                wd = pack2(w4.w); acc[3][0] = ffma2(wd, v0, acc[3][0]); acc[3][1] = ffma2(wd, v1, acc[3][1]);
            }
        }
        __syncthreads();   // col/wsm consumed; safe to overwrite next tap
    }

    // ---- epilogue: direct vectorized stores ----
    float4 b4 = *(const float4*)(bias + (cg << 2));
    float bb[4] = {b4.x, b4.y, b4.z, b4.w};
#pragma unroll
    for (int i = 0; i < 4; ++i) {
        float x0, x1, x2, x3;
        unpack2(acc[i][0], x0, x1);
        unpack2(acc[i][1], x2, x3);
        float4 o;
        o.x = x0 + bb[i]; o.y = x1 + bb[i]; o.z = x2 + bb[i]; o.w = x3 + bb[i];
        *(float4*)(out + ((size_t)n * COUT + (cg << 2) + i) * SP + s0 + (pg << 2)) = o;
    }
}

// ---------------------------------------------------------------------------
extern "C" void kernel_launch(void* const* d_in, const int* in_sizes, int n_in,
                              void* d_out, int out_size) {
    const float* x      = (const float*)d_in[0];
    const float* offset = (const float*)d_in[1];
    const float* weight = (const float*)d_in[2];
    const float* bias   = (const float*)d_in[3];
    float* out = (float*)d_out;

    dim3 gT(SP / 32, N_);
    transpose_x<<<gT, 256>>>(x);
    transpose_w<<<(KVOL * CIN * COUT + 255) / 256, 256>>>(weight);

    dim3 gM(SP / 64, N_);
    deform_conv3d_main<<<gM, 256>>>(offset, bias, out);
}